// round 16
// baseline (speedup 1.0000x reference)
#include <cuda_runtime.h>
#include <cuda_fp16.h>
#include <math.h>
#include <stdint.h>

// Problem constants
#define TT 512
#define BB 64
#define VV 256
#define HH 1024
#define NCTA 64

// ---------------------------------------------------------------------------
// Static device state. Packed weights are written by the PERSISTENT KERNEL
// ITSELF (phase 0) — each CTA packs and later reads ONLY its own slice.
// Layout: Wp[nblk][jj][k], jj = G*16 + u -> gate row r = G*1024 + nblk*16 + u.
// Hidden state fp32 via __stcg/__ldcg (validated in R10/R11).
// ---------------------------------------------------------------------------
__device__ __half g_Whi0[(size_t)64 * 64 * 1280];
__device__ __half g_Wlo0[(size_t)64 * 64 * 1280];
__device__ __half g_Whi1[(size_t)64 * 64 * 2048];
__device__ __half g_Wlo1[(size_t)64 * 64 * 2048];
__device__ __half g_Whi2[(size_t)64 * 64 * 2048];
__device__ __half g_Wlo2[(size_t)64 * 64 * 2048];
__device__ float  g_hf[3][2][BB * HH];            // ping-pong hidden, fp32
__device__ float  g_yT[(size_t)BB * HH * TT];     // masked top h: [b][u][t]
__device__ unsigned g_bar_cnt;
__device__ unsigned g_bar_gen;

struct Params {
    const float* inputs;
    const int*   lengths;
    const float *Wih0, *Whh0, *bih0, *bhh0;
    const float *Wihr, *Whhr, *bihr, *bhhr;
    const float *Wout, *bout;
};

__device__ __forceinline__ float sigf(float x) { return 1.0f / (1.0f + expf(-x)); }
__device__ __forceinline__ void mma16816(float* d, const uint32_t* a, const uint32_t* b) {
    asm volatile(
        "mma.sync.aligned.m16n8k16.row.col.f32.f16.f16.f32 "
        "{%0,%1,%2,%3}, {%4,%5,%6,%7}, {%8,%9}, {%0,%1,%2,%3};\n"
        : "+f"(d[0]), "+f"(d[1]), "+f"(d[2]), "+f"(d[3])
        : "r"(a[0]), "r"(a[1]), "r"(a[2]), "r"(a[3]), "r"(b[0]), "r"(b[1]));
}

// Grid barrier (64 co-resident CTAs) — validated.
__device__ __forceinline__ void grid_bar(unsigned target) {
    __syncthreads();
    if (threadIdx.x == 0) {
        __threadfence();
        unsigned old = atomicAdd(&g_bar_cnt, 1u);
        if (old == NCTA - 1) {
            g_bar_cnt = 0;
            __threadfence();
            atomicExch(&g_bar_gen, target);
        } else {
            while (atomicAdd(&g_bar_gen, 0u) != target) {}
        }
        __threadfence();
    }
    __syncthreads();
}

__global__ void init_kernel() {
    int i = blockIdx.x * blockDim.x + threadIdx.x;
    float* h = (float*)g_hf;
    for (int k = i; k < 3 * 2 * BB * HH; k += gridDim.x * blockDim.x) h[k] = 0.0f;
    if (i == 0) { g_bar_cnt = 0; g_bar_gen = 0; }
}

// ---------------------------------------------------------------------------
// Persistent LSTM: 64 CTAs x 256 threads, CTA nblk owns 16 units (64 packed
// gate cols). Phase 0: CTA packs ITS OWN hi/lo weight slices (producer ==
// consumer; no cross-kernel global dependency). Phase 1: per (t,l) fp16 mma
// GEMM, 3-pass hi/lo (fp32-accurate), cell pointwise with c in registers.
// Static smem 36864B: Ah/Al/Wh/Wl [64x72] fp16; Gs[64x68] f32 aliases Ah+Al.
// ---------------------------------------------------------------------------
__global__ void __launch_bounds__(256, 1) lstm_persistent(Params p) {
    __shared__ __align__(16) char smem_raw[4 * 64 * 72 * 2];
    __half* Ah = (__half*)smem_raw;
    __half* Al = Ah + 64 * 72;
    __half* Wh = Al + 64 * 72;
    __half* Wl = Wh + 64 * 72;
    float*  Gs = (float*)smem_raw;           // aliases Ah+Al (17408 <= 18432)

    const int tid  = threadIdx.x;
    const int lane = tid & 31, warp = tid >> 5;
    const int wm = warp & 1;      // M half: rows wm*32
    const int wn = warp >> 1;     // N quarter: cols wn*16
    const int grp = lane >> 2, tg = lane & 3;
    const int nblk = blockIdx.x;

    unsigned target = 0;

    // ---------------- Phase 0: self-pack this CTA's weight slices ----------
    for (int l = 0; l < 3; l++) {
        const float *Wih, *Whh;
        __half *Whi, *Wlo;
        int Kih, K;
        if (l == 0) {
            Wih = p.Wih0; Whh = p.Whh0; Kih = VV; K = 1280;
            Whi = g_Whi0 + (size_t)nblk * (64 * 1280);
            Wlo = g_Wlo0 + (size_t)nblk * (64 * 1280);
        } else if (l == 1) {
            Wih = p.Wihr; Whh = p.Whhr; Kih = HH; K = 2048;
            Whi = g_Whi1 + (size_t)nblk * (64 * 2048);
            Wlo = g_Wlo1 + (size_t)nblk * (64 * 2048);
        } else {
            Wih = p.Wihr + (size_t)4 * HH * HH; Whh = p.Whhr + (size_t)4 * HH * HH;
            Kih = HH; K = 2048;
            Whi = g_Whi2 + (size_t)nblk * (64 * 2048);
            Wlo = g_Wlo2 + (size_t)nblk * (64 * 2048);
        }
        for (int jj = warp; jj < 64; jj += 8) {
            int G = jj >> 4, u = jj & 15;
            int r = G * HH + nblk * 16 + u;          // validated gate-row map
            __half* dh = Whi + (size_t)jj * K;
            __half* dl = Wlo + (size_t)jj * K;
            for (int k = lane; k < K; k += 32) {
                float v = (k < Kih) ? Wih[(size_t)r * Kih + k]
                                    : Whh[(size_t)r * HH + (k - Kih)];
                __half hi = __float2half_rn(v);
                dh[k] = hi;
                dl[k] = __float2half_rn(v - __half2float(hi));
            }
        }
    }
    grid_bar(++target);   // includes __threadfence; packs visible (self anyway)

    // ---------------- Phase 1: recurrence ----------------------------------
    // Load maps
    const int arow = tid >> 2, aq = tid & 3;      // A: 64 rows x 4 q (16 floats)
    int wrow[2], woct[2];
#pragma unroll
    for (int i = 0; i < 2; i++) {
        int idx = tid + i * 256;
        wrow[i] = idx >> 3;   // 0..63
        woct[i] = idx & 7;    // 0..7
    }

    // Pointwise ownership
    const int u  = tid & 15;
    const int bp = tid >> 4;      // 0..15
    const int uu = nblk * 16 + u;

    float bias[3][4];
#pragma unroll
    for (int G = 0; G < 4; G++) {
        bias[0][G] = p.bih0[G * HH + uu] + p.bhh0[G * HH + uu];
        bias[1][G] = p.bihr[G * HH + uu] + p.bhhr[G * HH + uu];
        bias[2][G] = p.bihr[4 * HH + G * HH + uu] + p.bhhr[4 * HH + G * HH + uu];
    }
    int len[4];
    float creg[3][4];
#pragma unroll
    for (int j = 0; j < 4; j++) {
        len[j] = p.lengths[bp + j * 16];
#pragma unroll
        for (int l = 0; l < 3; l++) creg[l][j] = 0.0f;
    }

    for (int t = 0; t < TT; t++) {
        const int pin = t & 1, pout = pin ^ 1;
        for (int l = 0; l < 3; l++) {    // NOT unrolled (I$; matches R10)
            const float *A0, *A1;
            const __half *Whp, *Wlp;
            int split, nch, Kw, astr0;
            if (l == 0) {
                split = VV; nch = 20; Kw = 1280; astr0 = VV;
                A0 = p.inputs + (size_t)t * BB * VV;
                A1 = g_hf[0][pin];
                Whp = g_Whi0 + (size_t)nblk * (64 * 1280);
                Wlp = g_Wlo0 + (size_t)nblk * (64 * 1280);
            } else if (l == 1) {
                split = HH; nch = 32; Kw = 2048; astr0 = HH;
                A0 = g_hf[0][pout];
                A1 = g_hf[1][pin];
                Whp = g_Whi1 + (size_t)nblk * (64 * 2048);
                Wlp = g_Wlo1 + (size_t)nblk * (64 * 2048);
            } else {
                split = HH; nch = 32; Kw = 2048; astr0 = HH;
                A0 = g_hf[1][pout];
                A1 = g_hf[2][pin];
                Whp = g_Whi2 + (size_t)nblk * (64 * 2048);
                Wlp = g_Wlo2 + (size_t)nblk * (64 * 2048);
            }

            float acc[2][2][4];
#pragma unroll
            for (int a = 0; a < 2; a++)
#pragma unroll
                for (int b = 0; b < 2; b++)
#pragma unroll
                    for (int c = 0; c < 4; c++) acc[a][b][c] = 0.0f;

            float4 apre[4];
            uint4  whpre[2], wlpre[2];
            auto fetch = [&](int c) {
                int k0 = c * 64;
                const float* Ab; int as, kk;
                if (k0 < split) { Ab = A0; as = astr0; kk = k0; }
                else            { Ab = A1; as = HH;    kk = k0 - split; }
                const float* ar = Ab + (size_t)arow * as + kk + aq * 16;
#pragma unroll
                for (int i = 0; i < 4; i++) apre[i] = __ldcg((const float4*)(ar + i * 4));
#pragma unroll
                for (int i = 0; i < 2; i++) {
                    size_t wsrc = (size_t)wrow[i] * Kw + k0 + woct[i] * 8;
                    whpre[i] = __ldcg((const uint4*)(Whp + wsrc));
                    wlpre[i] = __ldcg((const uint4*)(Wlp + wsrc));
                }
            };
            auto stash = [&]() {
#pragma unroll
                for (int i = 0; i < 4; i++) {
                    float4 v = apre[i];
                    __half hx = __float2half_rn(v.x), hy = __float2half_rn(v.y);
                    __half hz = __float2half_rn(v.z), hw = __float2half_rn(v.w);
                    int o = arow * 72 + aq * 16 + i * 4;
                    *(__half2*)&Ah[o]     = __halves2half2(hx, hy);
                    *(__half2*)&Ah[o + 2] = __halves2half2(hz, hw);
                    *(__half2*)&Al[o]     = __floats2half2_rn(v.x - __half2float(hx),
                                                              v.y - __half2float(hy));
                    *(__half2*)&Al[o + 2] = __floats2half2_rn(v.z - __half2float(hz),
                                                              v.w - __half2float(hw));
                }
#pragma unroll
                for (int i = 0; i < 2; i++) {
                    int o = wrow[i] * 72 + woct[i] * 8;
                    *(uint4*)&Wh[o] = whpre[i];
                    *(uint4*)&Wl[o] = wlpre[i];
                }
            };
            auto compute = [&]() {
#pragma unroll
                for (int kk = 0; kk < 4; kk++) {
                    const int kb = kk * 16 + 2 * tg;
                    uint32_t ah[2][4], al[2][4], wh[2][2], wl[2][2];
#pragma unroll
                    for (int mi = 0; mi < 2; mi++) {
                        int r = wm * 32 + mi * 16 + grp;
                        ah[mi][0] = *(const uint32_t*)(Ah + r * 72 + kb);
                        ah[mi][1] = *(const uint32_t*)(Ah + (r + 8) * 72 + kb);
                        ah[mi][2] = *(const uint32_t*)(Ah + r * 72 + kb + 8);
                        ah[mi][3] = *(const uint32_t*)(Ah + (r + 8) * 72 + kb + 8);
                        al[mi][0] = *(const uint32_t*)(Al + r * 72 + kb);
                        al[mi][1] = *(const uint32_t*)(Al + (r + 8) * 72 + kb);
                        al[mi][2] = *(const uint32_t*)(Al + r * 72 + kb + 8);
                        al[mi][3] = *(const uint32_t*)(Al + (r + 8) * 72 + kb + 8);
                    }
#pragma unroll
                    for (int ni = 0; ni < 2; ni++) {
                        int n = wn * 16 + ni * 8 + grp;
                        wh[ni][0] = *(const uint32_t*)(Wh + n * 72 + kb);
                        wh[ni][1] = *(const uint32_t*)(Wh + n * 72 + kb + 8);
                        wl[ni][0] = *(const uint32_t*)(Wl + n * 72 + kb);
                        wl[ni][1] = *(const uint32_t*)(Wl + n * 72 + kb + 8);
                    }
#pragma unroll
                    for (int mi = 0; mi < 2; mi++)
#pragma unroll
                        for (int ni = 0; ni < 2; ni++) {
                            mma16816(acc[mi][ni], ah[mi], wh[ni]);  // Ahi*Whi
                            mma16816(acc[mi][ni], ah[mi], wl[ni]);  // Ahi*Wlo
                            mma16816(acc[mi][ni], al[mi], wh[ni]);  // Alo*Whi
                        }
                }
            };

            fetch(0);
            for (int c = 0; c < nch; c++) {
                stash();
                __syncthreads();
                if (c + 1 < nch) fetch(c + 1);   // LDGs overlap compute
                compute();
                __syncthreads();
            }

            // Regroup gates -> Gs (aliases A smem; safe after last sync)
#pragma unroll
            for (int mi = 0; mi < 2; mi++) {
                int r = wm * 32 + mi * 16 + grp;
#pragma unroll
                for (int ni = 0; ni < 2; ni++) {
                    int cc = wn * 16 + ni * 8 + 2 * tg;
                    Gs[r * 68 + cc]           = acc[mi][ni][0];
                    Gs[r * 68 + cc + 1]       = acc[mi][ni][1];
                    Gs[(r + 8) * 68 + cc]     = acc[mi][ni][2];
                    Gs[(r + 8) * 68 + cc + 1] = acc[mi][ni][3];
                }
            }
            __syncthreads();

            // Cell pointwise (fp32); h written fp32 via __stcg (validated)
            float* hout = g_hf[l][pout];
#pragma unroll
            for (int j = 0; j < 4; j++) {
                int b = bp + j * 16;
                float ii = Gs[b * 68 + u]      + bias[l][0];
                float ff = Gs[b * 68 + 16 + u] + bias[l][1];
                float gg = Gs[b * 68 + 32 + u] + bias[l][2];
                float oo = Gs[b * 68 + 48 + u] + bias[l][3];
                float cn = sigf(ff) * creg[l][j] + sigf(ii) * tanhf(gg);
                float hn = sigf(oo) * tanhf(cn);
                creg[l][j] = cn;
                size_t ci = (size_t)b * HH + uu;
                __stcg(&hout[ci], hn);
                if (l == 2)
                    g_yT[ci * TT + t] = (t < len[j]) ? hn : 0.0f;
            }
            grid_bar(++target);
        }
    }
}

// ---------------------------------------------------------------------------
// Projection (validated): out[b][v][t] = sum_u Wout[v][u]*yT[b][u][t]+bout[v]
// ---------------------------------------------------------------------------
__global__ void __launch_bounds__(256, 1) proj_kernel(Params p, float* __restrict__ out) {
    __shared__ float Wv[32 * 68];
    __shared__ float Yt[64 * 68];

    const int blk = blockIdx.x;
    const int b  = blk >> 6;
    const int vt = (blk >> 3) & 7;
    const int tt = blk & 7;
    const int tid = threadIdx.x;

    const int yrow = tid >> 2, yq = tid & 3;
    const int wrow = tid >> 3, wq = tid & 7;
    const int vr = tid >> 5;
    const int tc = tid & 31;

    float acc[4][2];
#pragma unroll
    for (int j = 0; j < 4; j++) { acc[j][0] = 0.0f; acc[j][1] = 0.0f; }

    const float* ybase = g_yT + (size_t)b * HH * TT;
    float4 ypre[4], wpre[2];
    auto fetch = [&](int c) {
        int k0 = c * 64;
        const float* yr = ybase + (size_t)(k0 + yrow) * TT + tt * 64 + yq * 16;
#pragma unroll
        for (int i = 0; i < 4; i++) ypre[i] = *(const float4*)(yr + i * 4);
        const float* wr = p.Wout + (size_t)(vt * 32 + wrow) * HH + k0 + wq * 8;
#pragma unroll
        for (int i = 0; i < 2; i++) wpre[i] = *(const float4*)(wr + i * 4);
    };
    auto stash = [&]() {
#pragma unroll
        for (int i = 0; i < 4; i++) *(float4*)&Yt[yrow * 68 + yq * 16 + i * 4] = ypre[i];
#pragma unroll
        for (int i = 0; i < 2; i++) *(float4*)&Wv[wrow * 68 + wq * 8 + i * 4] = wpre[i];
    };

    fetch(0);
    for (int c = 0; c < 16; c++) {
        stash();
        __syncthreads();
        if (c + 1 < 16) fetch(c + 1);
#pragma unroll 8
        for (int k = 0; k < 64; k++) {
            float y0 = Yt[k * 68 + tc * 2];
            float y1 = Yt[k * 68 + tc * 2 + 1];
#pragma unroll
            for (int j = 0; j < 4; j++) {
                float w = Wv[(vr * 4 + j) * 68 + k];
                acc[j][0] += w * y0;
                acc[j][1] += w * y1;
            }
        }
        __syncthreads();
    }

#pragma unroll
    for (int j = 0; j < 4; j++) {
        int v = vt * 32 + vr * 4 + j;
        float bo = p.bout[v];
        size_t o = ((size_t)b * VV + v) * TT + tt * 64 + tc * 2;
        out[o]     = acc[j][0] + bo;
        out[o + 1] = acc[j][1] + bo;
    }
}

// ---------------------------------------------------------------------------
// Launch: 3 graph nodes. Size-based input resolution (validated).
// ---------------------------------------------------------------------------
extern "C" void kernel_launch(void* const* d_in, const int* in_sizes, int n_in,
                              void* d_out, int out_size) {
    Params p = {};
    int nbig = 0, n4k = 0, n8k = 0;
    for (int i = 0; i < n_in; i++) {
        const void* ptr = d_in[i];
        switch (in_sizes[i]) {
            case 8388608:
                if (nbig == 0)      p.inputs = (const float*)ptr;
                else if (nbig == 1) p.Wihr   = (const float*)ptr;
                else                p.Whhr   = (const float*)ptr;
                nbig++; break;
            case 64:      p.lengths = (const int*)ptr;   break;
            case 1048576: p.Wih0    = (const float*)ptr; break;
            case 4194304: p.Whh0    = (const float*)ptr; break;
            case 4096:
                if (n4k == 0) p.bih0 = (const float*)ptr; else p.bhh0 = (const float*)ptr;
                n4k++; break;
            case 8192:
                if (n8k == 0) p.bihr = (const float*)ptr; else p.bhhr = (const float*)ptr;
                n8k++; break;
            case 262144:  p.Wout = (const float*)ptr; break;
            case 256:     p.bout = (const float*)ptr; break;
            default: break;
        }
    }

    init_kernel<<<256, 256>>>();
    lstm_persistent<<<NCTA, 256>>>(p);
    proj_kernel<<<64 * 8 * 8, 256>>>(p, (float*)d_out);
}

// round 17
// speedup vs baseline: 1.1903x; 1.1903x over previous
#include <cuda_runtime.h>
#include <cuda_fp16.h>
#include <math.h>
#include <stdint.h>

// Problem constants
#define TT 512
#define BB 64
#define VV 256
#define HH 1024
#define NCTA 128

// ---------------------------------------------------------------------------
// Static device state. Packed weights are written by the PERSISTENT KERNEL
// ITSELF (phase 0) — each CTA packs and later reads ONLY its own slice.
// Slice layout per CTA (nblk 0..127): 32 cols x K, col jj = G*8 + u ->
// gate row r = G*1024 + nblk*8 + u. Hidden state fp32 via __stcg/__ldcg.
// ---------------------------------------------------------------------------
__device__ __half g_Whi0[(size_t)128 * 32 * 1280];
__device__ __half g_Wlo0[(size_t)128 * 32 * 1280];
__device__ __half g_Whi1[(size_t)128 * 32 * 2048];
__device__ __half g_Wlo1[(size_t)128 * 32 * 2048];
__device__ __half g_Whi2[(size_t)128 * 32 * 2048];
__device__ __half g_Wlo2[(size_t)128 * 32 * 2048];
__device__ float  g_hf[3][2][BB * HH];            // ping-pong hidden, fp32
__device__ float  g_yT[(size_t)BB * HH * TT];     // masked top h: [b][u][t]
__device__ unsigned g_bar_cnt;
__device__ unsigned g_bar_gen;

struct Params {
    const float* inputs;
    const int*   lengths;
    const float *Wih0, *Whh0, *bih0, *bhh0;
    const float *Wihr, *Whhr, *bihr, *bhhr;
    const float *Wout, *bout;
};

__device__ __forceinline__ float sigf(float x) { return 1.0f / (1.0f + expf(-x)); }
__device__ __forceinline__ void mma16816(float* d, const uint32_t* a, const uint32_t* b) {
    asm volatile(
        "mma.sync.aligned.m16n8k16.row.col.f32.f16.f16.f32 "
        "{%0,%1,%2,%3}, {%4,%5,%6,%7}, {%8,%9}, {%0,%1,%2,%3};\n"
        : "+f"(d[0]), "+f"(d[1]), "+f"(d[2]), "+f"(d[3])
        : "r"(a[0]), "r"(a[1]), "r"(a[2]), "r"(a[3]), "r"(b[0]), "r"(b[1]));
}

// Grid barrier (128 co-resident CTAs) — validated at 128 in R11.
__device__ __forceinline__ void grid_bar(unsigned target) {
    __syncthreads();
    if (threadIdx.x == 0) {
        __threadfence();
        unsigned old = atomicAdd(&g_bar_cnt, 1u);
        if (old == NCTA - 1) {
            g_bar_cnt = 0;
            __threadfence();
            atomicExch(&g_bar_gen, target);
        } else {
            while (atomicAdd(&g_bar_gen, 0u) != target) {}
        }
        __threadfence();
    }
    __syncthreads();
}

__global__ void init_kernel() {
    int i = blockIdx.x * blockDim.x + threadIdx.x;
    float* h = (float*)g_hf;
    for (int k = i; k < 3 * 2 * BB * HH; k += gridDim.x * blockDim.x) h[k] = 0.0f;
    if (i == 0) { g_bar_cnt = 0; g_bar_gen = 0; }
}

// ---------------------------------------------------------------------------
// Persistent LSTM: 128 CTAs x 256 threads, CTA nblk owns 8 units (32 packed
// gate cols). Phase 0: self-pack hi/lo weight slices (R16-validated).
// Phase 1: per (t,l) fp16 mma GEMM (M=64 x N=32), 3-pass hi/lo
// (fp32-accurate), cell pointwise with c in registers.
// smem: Ah/Al [64x72] + Wh/Wl [32x72] fp16 (27648B); Gs[64x36] f32 aliases.
// ---------------------------------------------------------------------------
__global__ void __launch_bounds__(256, 1) lstm_persistent(Params p) {
    __shared__ __align__(16) char smem_raw[(2 * 64 * 72 + 2 * 32 * 72) * 2];
    __half* Ah = (__half*)smem_raw;
    __half* Al = Ah + 64 * 72;
    __half* Wh = Al + 64 * 72;
    __half* Wl = Wh + 32 * 72;
    float*  Gs = (float*)smem_raw;           // aliases Ah (9216 <= 9216) OK

    const int tid  = threadIdx.x;
    const int lane = tid & 31, warp = tid >> 5;
    const int wm = warp & 1;      // M half: rows wm*32
    const int wn = warp >> 1;     // N-8 block: cols wn*8 (0..3)
    const int grp = lane >> 2, tg = lane & 3;
    const int nblk = blockIdx.x;

    unsigned target = 0;

    // ---------------- Phase 0: self-pack this CTA's weight slices ----------
    for (int l = 0; l < 3; l++) {
        const float *Wih, *Whh;
        __half *Whi, *Wlo;
        int Kih, K;
        if (l == 0) {
            Wih = p.Wih0; Whh = p.Whh0; Kih = VV; K = 1280;
            Whi = g_Whi0 + (size_t)nblk * (32 * 1280);
            Wlo = g_Wlo0 + (size_t)nblk * (32 * 1280);
        } else if (l == 1) {
            Wih = p.Wihr; Whh = p.Whhr; Kih = HH; K = 2048;
            Whi = g_Whi1 + (size_t)nblk * (32 * 2048);
            Wlo = g_Wlo1 + (size_t)nblk * (32 * 2048);
        } else {
            Wih = p.Wihr + (size_t)4 * HH * HH; Whh = p.Whhr + (size_t)4 * HH * HH;
            Kih = HH; K = 2048;
            Whi = g_Whi2 + (size_t)nblk * (32 * 2048);
            Wlo = g_Wlo2 + (size_t)nblk * (32 * 2048);
        }
        for (int jj = warp; jj < 32; jj += 8) {
            int G = jj >> 3, u = jj & 7;
            int r = G * HH + nblk * 8 + u;           // validated gate-row map
            __half* dh = Whi + (size_t)jj * K;
            __half* dl = Wlo + (size_t)jj * K;
            for (int k = lane; k < K; k += 32) {
                float v = (k < Kih) ? Wih[(size_t)r * Kih + k]
                                    : Whh[(size_t)r * HH + (k - Kih)];
                __half hi = __float2half_rn(v);
                dh[k] = hi;
                dl[k] = __float2half_rn(v - __half2float(hi));
            }
        }
    }
    grid_bar(++target);

    // ---------------- Phase 1: recurrence ----------------------------------
    // Load maps
    const int arow = tid >> 2, aq = tid & 3;      // A: 64 rows x 4 q (16 floats)
    const int wrow = tid >> 3, woct = tid & 7;    // W: 32 rows x 8 octs (8 halves)

    // Pointwise ownership (R11-validated): unit u = tid&7, batches bp, bp+32
    const int u  = tid & 7;
    const int bp = tid >> 3;      // 0..31
    const int uu = nblk * 8 + u;

    float bias[3][4];
#pragma unroll
    for (int G = 0; G < 4; G++) {
        bias[0][G] = p.bih0[G * HH + uu] + p.bhh0[G * HH + uu];
        bias[1][G] = p.bihr[G * HH + uu] + p.bhhr[G * HH + uu];
        bias[2][G] = p.bihr[4 * HH + G * HH + uu] + p.bhhr[4 * HH + G * HH + uu];
    }
    int len[2] = { p.lengths[bp], p.lengths[bp + 32] };
    float creg[3][2];
#pragma unroll
    for (int l = 0; l < 3; l++) { creg[l][0] = 0.0f; creg[l][1] = 0.0f; }

    for (int t = 0; t < TT; t++) {
        const int pin = t & 1, pout = pin ^ 1;
        for (int l = 0; l < 3; l++) {    // not unrolled (I$)
            const float *A0, *A1;
            const __half *Whp, *Wlp;
            int split, nch, Kw, astr0;
            if (l == 0) {
                split = VV; nch = 20; Kw = 1280; astr0 = VV;
                A0 = p.inputs + (size_t)t * BB * VV;
                A1 = g_hf[0][pin];
                Whp = g_Whi0 + (size_t)nblk * (32 * 1280);
                Wlp = g_Wlo0 + (size_t)nblk * (32 * 1280);
            } else if (l == 1) {
                split = HH; nch = 32; Kw = 2048; astr0 = HH;
                A0 = g_hf[0][pout];
                A1 = g_hf[1][pin];
                Whp = g_Whi1 + (size_t)nblk * (32 * 2048);
                Wlp = g_Wlo1 + (size_t)nblk * (32 * 2048);
            } else {
                split = HH; nch = 32; Kw = 2048; astr0 = HH;
                A0 = g_hf[1][pout];
                A1 = g_hf[2][pin];
                Whp = g_Whi2 + (size_t)nblk * (32 * 2048);
                Wlp = g_Wlo2 + (size_t)nblk * (32 * 2048);
            }

            float acc[2][4];
#pragma unroll
            for (int mi = 0; mi < 2; mi++)
#pragma unroll
                for (int c = 0; c < 4; c++) acc[mi][c] = 0.0f;

            float4 apre[4];
            uint4  whpre, wlpre;
            auto fetch = [&](int c) {
                int k0 = c * 64;
                const float* Ab; int as, kk;
                if (k0 < split) { Ab = A0; as = astr0; kk = k0; }
                else            { Ab = A1; as = HH;    kk = k0 - split; }
                const float* ar = Ab + (size_t)arow * as + kk + aq * 16;
#pragma unroll
                for (int i = 0; i < 4; i++) apre[i] = __ldcg((const float4*)(ar + i * 4));
                size_t wsrc = (size_t)wrow * Kw + k0 + woct * 8;
                whpre = __ldcg((const uint4*)(Whp + wsrc));
                wlpre = __ldcg((const uint4*)(Wlp + wsrc));
            };
            auto stash = [&]() {
#pragma unroll
                for (int i = 0; i < 4; i++) {
                    float4 v = apre[i];
                    __half hx = __float2half_rn(v.x), hy = __float2half_rn(v.y);
                    __half hz = __float2half_rn(v.z), hw = __float2half_rn(v.w);
                    int o = arow * 72 + aq * 16 + i * 4;
                    *(__half2*)&Ah[o]     = __halves2half2(hx, hy);
                    *(__half2*)&Ah[o + 2] = __halves2half2(hz, hw);
                    *(__half2*)&Al[o]     = __floats2half2_rn(v.x - __half2float(hx),
                                                              v.y - __half2float(hy));
                    *(__half2*)&Al[o + 2] = __floats2half2_rn(v.z - __half2float(hz),
                                                              v.w - __half2float(hw));
                }
                int o = wrow * 72 + woct * 8;
                *(uint4*)&Wh[o] = whpre;
                *(uint4*)&Wl[o] = wlpre;
            };
            auto compute = [&]() {
#pragma unroll
                for (int kk = 0; kk < 4; kk++) {
                    const int kb = kk * 16 + 2 * tg;
                    uint32_t ah[2][4], al[2][4], wh[2], wl[2];
#pragma unroll
                    for (int mi = 0; mi < 2; mi++) {
                        int r = wm * 32 + mi * 16 + grp;
                        ah[mi][0] = *(const uint32_t*)(Ah + r * 72 + kb);
                        ah[mi][1] = *(const uint32_t*)(Ah + (r + 8) * 72 + kb);
                        ah[mi][2] = *(const uint32_t*)(Ah + r * 72 + kb + 8);
                        ah[mi][3] = *(const uint32_t*)(Ah + (r + 8) * 72 + kb + 8);
                        al[mi][0] = *(const uint32_t*)(Al + r * 72 + kb);
                        al[mi][1] = *(const uint32_t*)(Al + (r + 8) * 72 + kb);
                        al[mi][2] = *(const uint32_t*)(Al + r * 72 + kb + 8);
                        al[mi][3] = *(const uint32_t*)(Al + (r + 8) * 72 + kb + 8);
                    }
                    {
                        int n = wn * 8 + grp;
                        wh[0] = *(const uint32_t*)(Wh + n * 72 + kb);
                        wh[1] = *(const uint32_t*)(Wh + n * 72 + kb + 8);
                        wl[0] = *(const uint32_t*)(Wl + n * 72 + kb);
                        wl[1] = *(const uint32_t*)(Wl + n * 72 + kb + 8);
                    }
#pragma unroll
                    for (int mi = 0; mi < 2; mi++) {
                        mma16816(acc[mi], ah[mi], wh);   // Ahi*Whi
                        mma16816(acc[mi], ah[mi], wl);   // Ahi*Wlo
                        mma16816(acc[mi], al[mi], wh);   // Alo*Whi
                    }
                }
            };

            fetch(0);
            for (int c = 0; c < nch; c++) {
                stash();
                __syncthreads();
                if (c + 1 < nch) fetch(c + 1);   // LDGs overlap compute
                compute();
                __syncthreads();
            }

            // Regroup gates -> Gs (aliases A smem; safe after last sync)
#pragma unroll
            for (int mi = 0; mi < 2; mi++) {
                int r = wm * 32 + mi * 16 + grp;
                int cc = wn * 8 + 2 * tg;
                Gs[r * 36 + cc]           = acc[mi][0];
                Gs[r * 36 + cc + 1]       = acc[mi][1];
                Gs[(r + 8) * 36 + cc]     = acc[mi][2];
                Gs[(r + 8) * 36 + cc + 1] = acc[mi][3];
            }
            __syncthreads();

            // Cell pointwise (fp32); h written fp32 via __stcg (validated)
            float* hout = g_hf[l][pout];
#pragma unroll
            for (int j = 0; j < 2; j++) {
                int b = bp + j * 32;
                float ii = Gs[b * 36 + u]      + bias[l][0];
                float ff = Gs[b * 36 + 8 + u]  + bias[l][1];
                float gg = Gs[b * 36 + 16 + u] + bias[l][2];
                float oo = Gs[b * 36 + 24 + u] + bias[l][3];
                float cn = sigf(ff) * creg[l][j] + sigf(ii) * tanhf(gg);
                float hn = sigf(oo) * tanhf(cn);
                creg[l][j] = cn;
                size_t ci = (size_t)b * HH + uu;
                __stcg(&hout[ci], hn);
                if (l == 2)
                    g_yT[ci * TT + t] = (t < len[j]) ? hn : 0.0f;
            }
            grid_bar(++target);
        }
    }
}

// ---------------------------------------------------------------------------
// Projection (validated): out[b][v][t] = sum_u Wout[v][u]*yT[b][u][t]+bout[v]
// ---------------------------------------------------------------------------
__global__ void __launch_bounds__(256, 1) proj_kernel(Params p, float* __restrict__ out) {
    __shared__ float Wv[32 * 68];
    __shared__ float Yt[64 * 68];

    const int blk = blockIdx.x;
    const int b  = blk >> 6;
    const int vt = (blk >> 3) & 7;
    const int tt = blk & 7;
    const int tid = threadIdx.x;

    const int yrow = tid >> 2, yq = tid & 3;
    const int wrow = tid >> 3, wq = tid & 7;
    const int vr = tid >> 5;
    const int tc = tid & 31;

    float acc[4][2];
#pragma unroll
    for (int j = 0; j < 4; j++) { acc[j][0] = 0.0f; acc[j][1] = 0.0f; }

    const float* ybase = g_yT + (size_t)b * HH * TT;
    float4 ypre[4], wpre[2];
    auto fetch = [&](int c) {
        int k0 = c * 64;
        const float* yr = ybase + (size_t)(k0 + yrow) * TT + tt * 64 + yq * 16;
#pragma unroll
        for (int i = 0; i < 4; i++) ypre[i] = *(const float4*)(yr + i * 4);
        const float* wr = p.Wout + (size_t)(vt * 32 + wrow) * HH + k0 + wq * 8;
#pragma unroll
        for (int i = 0; i < 2; i++) wpre[i] = *(const float4*)(wr + i * 4);
    };
    auto stash = [&]() {
#pragma unroll
        for (int i = 0; i < 4; i++) *(float4*)&Yt[yrow * 68 + yq * 16 + i * 4] = ypre[i];
#pragma unroll
        for (int i = 0; i < 2; i++) *(float4*)&Wv[wrow * 68 + wq * 8 + i * 4] = wpre[i];
    };

    fetch(0);
    for (int c = 0; c < 16; c++) {
        stash();
        __syncthreads();
        if (c + 1 < 16) fetch(c + 1);
#pragma unroll 8
        for (int k = 0; k < 64; k++) {
            float y0 = Yt[k * 68 + tc * 2];
            float y1 = Yt[k * 68 + tc * 2 + 1];
#pragma unroll
            for (int j = 0; j < 4; j++) {
                float w = Wv[(vr * 4 + j) * 68 + k];
                acc[j][0] += w * y0;
                acc[j][1] += w * y1;
            }
        }
        __syncthreads();
    }

#pragma unroll
    for (int j = 0; j < 4; j++) {
        int v = vt * 32 + vr * 4 + j;
        float bo = p.bout[v];
        size_t o = ((size_t)b * VV + v) * TT + tt * 64 + tc * 2;
        out[o]     = acc[j][0] + bo;
        out[o + 1] = acc[j][1] + bo;
    }
}

// ---------------------------------------------------------------------------
// Launch: 3 graph nodes. Size-based input resolution (validated).
// ---------------------------------------------------------------------------
extern "C" void kernel_launch(void* const* d_in, const int* in_sizes, int n_in,
                              void* d_out, int out_size) {
    Params p = {};
    int nbig = 0, n4k = 0, n8k = 0;
    for (int i = 0; i < n_in; i++) {
        const void* ptr = d_in[i];
        switch (in_sizes[i]) {
            case 8388608:
                if (nbig == 0)      p.inputs = (const float*)ptr;
                else if (nbig == 1) p.Wihr   = (const float*)ptr;
                else                p.Whhr   = (const float*)ptr;
                nbig++; break;
            case 64:      p.lengths = (const int*)ptr;   break;
            case 1048576: p.Wih0    = (const float*)ptr; break;
            case 4194304: p.Whh0    = (const float*)ptr; break;
            case 4096:
                if (n4k == 0) p.bih0 = (const float*)ptr; else p.bhh0 = (const float*)ptr;
                n4k++; break;
            case 8192:
                if (n8k == 0) p.bihr = (const float*)ptr; else p.bhhr = (const float*)ptr;
                n8k++; break;
            case 262144:  p.Wout = (const float*)ptr; break;
            case 256:     p.bout = (const float*)ptr; break;
            default: break;
        }
    }

    init_kernel<<<256, 256>>>();
    lstm_persistent<<<NCTA, 256>>>(p);
    proj_kernel<<<64 * 8 * 8, 256>>>(p, (float*)d_out);
}